// round 8
// baseline (speedup 1.0000x reference)
#include <cuda_runtime.h>
#include <cuda_fp16.h>
#include <cstdint>

// Sinkhorn-Knopp, fp16 matrix. ONE DRAM sweep per iteration via cp.async SMEM
// staging (R6) + 2 CTAs/SM latency overlap (R5) + thread-private buffer
// ownership (no buffer barriers: each thread copies exactly the chunks it
// reads). 2 barriers per 2-row group (row-partial publish, eu publish).
//   E' = 1024*exp(-10*C) fp16; global scale cancels exactly.
//   iter: per group: eu_r = (d_r+eps)/sum_j E_rj evh_j ; colacc_j += eu_r E_rj
//   col_reduce: ev_j = (s_j+eps)/sum_{cta} part[cta][j] (fixed order)
//   P = eu_i E'_ij ev_j

#define NN 8192
#define NC4 (NN / 8)                 // 1024 uint4 chunks (8 halves) per row
#define GROWS 2                      // rows per group (32 KB)
#define NGROUPS (NN / GROWS)         // 4096
#define NCTAS 296                    // 2 CTAs per SM
#define NTHR 512
#define EPS 1e-6f
#define ESCALE 1024.0f

// smem layout (bytes): 3 buffers x 2 rows x 1024 uint4 = 98304
#define SM_BUF   0
#define SM_WPART 98304               // float[2][16]
#define SM_EUS   98432               // float[2]
#define SM_TOTAL 98560

__device__ __align__(16) __half g_E[(size_t)NN * NN];        // 128 MB
__device__ __align__(16) float  g_eu[NN];
__device__ __align__(16) float  g_ev[NN];                    // fp32 (final)
__device__ __align__(16) __half g_evh[NN];                   // fp16 (hot loop)
__device__ __align__(16) float  g_part[(size_t)NCTAS * NN];  // 9.7 MB

__device__ __forceinline__ void cpa16(uint32_t smem_dst, const void* gsrc) {
    asm volatile("cp.async.cg.shared.global [%0], [%1], 16;\n"
                 :: "r"(smem_dst), "l"(gsrc));
}
#define CP_COMMIT() asm volatile("cp.async.commit_group;\n" ::: "memory")
#define CP_WAIT2()  asm volatile("cp.async.wait_group 2;\n" ::: "memory")

// FMA-only exp for x in [-15, 0]
__device__ __forceinline__ float fast_exp_neg(float x) {
    const float LOG2E = 1.4426950408889634f;
    float t = x * LOG2E;
    float n = rintf(t);
    float f = t - n;
    float p = 1.5403530393381608e-4f;
    p = fmaf(p, f, 1.3333558146428443e-3f);
    p = fmaf(p, f, 9.6181291076284770e-3f);
    p = fmaf(p, f, 5.5504108664821580e-2f);
    p = fmaf(p, f, 2.4022650695910070e-1f);
    p = fmaf(p, f, 6.9314718055994530e-1f);
    p = fmaf(p, f, 1.0f);
    return p * __int_as_float(((int)n + 127) << 23);
}

// ---------------------------------------------------------------------------
__global__ void precompute_kernel(const float* __restrict__ C) {
    size_t g = (size_t)blockIdx.x * blockDim.x + threadIdx.x;
    const float4* C4 = reinterpret_cast<const float4*>(C);
    float4 c0 = C4[2 * g];
    float4 c1 = C4[2 * g + 1];
    __half2 h[4];
    h[0] = __floats2half2_rn(ESCALE * fast_exp_neg(-10.0f * c0.x),
                             ESCALE * fast_exp_neg(-10.0f * c0.y));
    h[1] = __floats2half2_rn(ESCALE * fast_exp_neg(-10.0f * c0.z),
                             ESCALE * fast_exp_neg(-10.0f * c0.w));
    h[2] = __floats2half2_rn(ESCALE * fast_exp_neg(-10.0f * c1.x),
                             ESCALE * fast_exp_neg(-10.0f * c1.y));
    h[3] = __floats2half2_rn(ESCALE * fast_exp_neg(-10.0f * c1.z),
                             ESCALE * fast_exp_neg(-10.0f * c1.w));
    reinterpret_cast<uint4*>(g_E)[g] = *reinterpret_cast<uint4*>(h);
    if (g < NN) {
        const float E1 = 2.718281828459045f;      // exp(v0), v0 = 1
        g_ev[g]  = E1;
        g_evh[g] = __float2half_rn(E1);
    }
}

// ---------------------------------------------------------------------------
// Fused iteration kernel: 296 CTAs x 512 threads, 2 CTAs/SM.
// CTA c handles 2-row groups {c, c+296, ...}. Thread t owns chunks t and
// t+512 of every row it touches (copies them, reads them -> no buf barriers).
// ---------------------------------------------------------------------------
__global__ void __launch_bounds__(NTHR, 2)
iter_kernel(const float* __restrict__ d) {
    extern __shared__ char smraw[];
    uint4* buf   = reinterpret_cast<uint4*>(smraw + SM_BUF);   // [3][2][1024]
    float* wpart = reinterpret_cast<float*>(smraw + SM_WPART); // [2][16]
    float* eu_s  = reinterpret_cast<float*>(smraw + SM_EUS);   // [2]

    const int tid  = threadIdx.x;
    const int wid  = tid >> 5;
    const int lane = tid & 31;
    const int cta  = blockIdx.x;
    const int ng   = (NGROUPS - cta + NCTAS - 1) / NCTAS;      // 13 or 14

    const uint4* Eg  = reinterpret_cast<const uint4*>(g_E);
    const uint4* EVH = reinterpret_cast<const uint4*>(g_evh);

    const uint32_t smbase = (uint32_t)__cvta_generic_to_shared(buf);

    auto prefetch = [&](int t) {
        const int grow0 = (cta + t * NCTAS) * GROWS;
        const uint32_t sb = smbase + (uint32_t)((t % 3) * 2048) * 16u;
#pragma unroll
        for (int r = 0; r < GROWS; ++r) {
            const uint4* src = Eg + (size_t)(grow0 + r) * NC4;
            cpa16(sb + (uint32_t)(r * 1024 + tid) * 16u,       src + tid);
            cpa16(sb + (uint32_t)(r * 1024 + tid + 512) * 16u, src + tid + 512);
        }
    };

    prefetch(0); CP_COMMIT();
    prefetch(1); CP_COMMIT();

    float ca[8] = {0.f, 0.f, 0.f, 0.f, 0.f, 0.f, 0.f, 0.f};   // cols of chunk tid
    float cb[8] = {0.f, 0.f, 0.f, 0.f, 0.f, 0.f, 0.f, 0.f};   // cols of chunk tid+512

    for (int t = 0; t < ng; ++t) {
        if (t + 2 < ng) prefetch(t + 2);
        CP_COMMIT();
        CP_WAIT2();                   // own copies of group t complete

        const uint4* B = buf + (t % 3) * 2048;
        const int grow0 = (cta + t * NCTAS) * GROWS;

        // ---- phase 1: row partials (each thread: 2 chunks x 2 rows) -------
        float rp0 = 0.f, rp1 = 0.f;
        float va[8], vb[8];
        {
            uint4 ev = __ldg(EVH + tid);
            const __half2* hv = reinterpret_cast<const __half2*>(&ev);
#pragma unroll
            for (int k = 0; k < 4; ++k) {
                float2 v = __half22float2(hv[k]);
                va[2 * k] = v.x; va[2 * k + 1] = v.y;
            }
            ev = __ldg(EVH + tid + 512);
            hv = reinterpret_cast<const __half2*>(&ev);
#pragma unroll
            for (int k = 0; k < 4; ++k) {
                float2 v = __half22float2(hv[k]);
                vb[2 * k] = v.x; vb[2 * k + 1] = v.y;
            }
        }
#pragma unroll
        for (int r = 0; r < GROWS; ++r) {
            uint4 eA = B[r * 1024 + tid];
            uint4 eB = B[r * 1024 + tid + 512];
            const __half2* ha = reinterpret_cast<const __half2*>(&eA);
            const __half2* hb = reinterpret_cast<const __half2*>(&eB);
            float acc = 0.f;
#pragma unroll
            for (int k = 0; k < 4; ++k) {
                float2 fa = __half22float2(ha[k]);
                float2 fb = __half22float2(hb[k]);
                acc = fmaf(fa.x, va[2 * k], acc);
                acc = fmaf(fa.y, va[2 * k + 1], acc);
                acc = fmaf(fb.x, vb[2 * k], acc);
                acc = fmaf(fb.y, vb[2 * k + 1], acc);
            }
            if (r == 0) rp0 = acc; else rp1 = acc;
        }
#pragma unroll
        for (int o = 16; o > 0; o >>= 1) {
            rp0 += __shfl_down_sync(0xFFFFFFFFu, rp0, o);
            rp1 += __shfl_down_sync(0xFFFFFFFFu, rp1, o);
        }
        if (lane == 0) {
            wpart[wid]      = rp0;
            wpart[16 + wid] = rp1;
        }
        __syncthreads();

        if (wid == 0) {               // warp 0: two 16-wide reductions
            float x = wpart[lane];    // lanes 0-15: row0, 16-31: row1
#pragma unroll
            for (int o = 8; o > 0; o >>= 1)
                x += __shfl_down_sync(0xFFFFFFFFu, x, o, 16);
            if ((lane & 15) == 0) {
                int r = lane >> 4;
                float eu = (d[grow0 + r] + EPS) / x;
                eu_s[r] = eu;
                g_eu[grow0 + r] = eu;
            }
        }
        __syncthreads();

        // ---- phase 2: column accumulation (registers, persistent) ---------
        float u0 = eu_s[0], u1 = eu_s[1];
#pragma unroll
        for (int r = 0; r < GROWS; ++r) {
            float u = (r == 0) ? u0 : u1;
            uint4 eA = B[r * 1024 + tid];
            uint4 eB = B[r * 1024 + tid + 512];
            const __half2* ha = reinterpret_cast<const __half2*>(&eA);
            const __half2* hb = reinterpret_cast<const __half2*>(&eB);
#pragma unroll
            for (int k = 0; k < 4; ++k) {
                float2 fa = __half22float2(ha[k]);
                float2 fb = __half22float2(hb[k]);
                ca[2 * k]     = fmaf(fa.x, u, ca[2 * k]);
                ca[2 * k + 1] = fmaf(fa.y, u, ca[2 * k + 1]);
                cb[2 * k]     = fmaf(fb.x, u, cb[2 * k]);
                cb[2 * k + 1] = fmaf(fb.y, u, cb[2 * k + 1]);
            }
        }
        // no trailing barrier: thread-private buffer chunks
    }

    // write CTA column partials: chunk tid -> cols 8*tid.., chunk tid+512
    float4* P4 = reinterpret_cast<float4*>(g_part + (size_t)cta * NN);
    P4[2 * tid]             = make_float4(ca[0], ca[1], ca[2], ca[3]);
    P4[2 * tid + 1]         = make_float4(ca[4], ca[5], ca[6], ca[7]);
    P4[2 * (tid + 512)]     = make_float4(cb[0], cb[1], cb[2], cb[3]);
    P4[2 * (tid + 512) + 1] = make_float4(cb[4], cb[5], cb[6], cb[7]);
}

// ---------------------------------------------------------------------------
// ev_j = (s_j+eps) / sum over 296 CTA partials (fixed order, deterministic).
// grid = 64 CTAs x 256 threads; 8 slices x 37 partials; fixed-order combine.
// ---------------------------------------------------------------------------
__global__ void col_reduce_kernel(const float* __restrict__ s) {
    __shared__ float4 red[8][32];
    const int g     = threadIdx.x & 31;
    const int slice = threadIdx.x >> 5;          // 0..7
    const int col4  = blockIdx.x * 32 + g;       // 0..2047
    const float4* P4 = reinterpret_cast<const float4*>(g_part);
    float4 acc = make_float4(0.f, 0.f, 0.f, 0.f);
#pragma unroll
    for (int k = 0; k < 37; ++k) {
        float4 v = P4[(size_t)(slice * 37 + k) * (NN / 4) + col4];
        acc.x += v.x; acc.y += v.y; acc.z += v.z; acc.w += v.w;
    }
    red[slice][g] = acc;
    __syncthreads();
    if (slice == 0) {
        float4 t = red[0][g];
#pragma unroll
        for (int q = 1; q < 8; ++q) {            // fixed order
            float4 r = red[q][g];
            t.x += r.x; t.y += r.y; t.z += r.z; t.w += r.w;
        }
        int j0 = col4 * 4;
        float e0 = (s[j0 + 0] + EPS) / t.x;
        float e1 = (s[j0 + 1] + EPS) / t.y;
        float e2 = (s[j0 + 2] + EPS) / t.z;
        float e3 = (s[j0 + 3] + EPS) / t.w;
        reinterpret_cast<float4*>(g_ev)[col4] = make_float4(e0, e1, e2, e3);
        __half2* VH2 = reinterpret_cast<__half2*>(g_evh);
        VH2[2 * col4]     = __floats2half2_rn(e0, e1);
        VH2[2 * col4 + 1] = __floats2half2_rn(e2, e3);
    }
}

// ---------------------------------------------------------------------------
// Final: P_ij = eu_i * E'_ij * ev_j   (fp32 eu/ev)
// ---------------------------------------------------------------------------
__global__ void final_kernel(float* __restrict__ out) {
    size_t idx = (size_t)blockIdx.x * blockDim.x + threadIdx.x;
    int row = (int)(idx / NC4);
    int c8  = (int)(idx % NC4);
    float u = g_eu[row];
    const float4* ev4 = reinterpret_cast<const float4*>(g_ev);
    float4 v0 = ev4[2 * c8];
    float4 v1 = ev4[2 * c8 + 1];
    uint4 e = reinterpret_cast<const uint4*>(g_E)[idx];
    const __half2* hp = reinterpret_cast<const __half2*>(&e);
    float2 f0 = __half22float2(hp[0]);
    float2 f1 = __half22float2(hp[1]);
    float2 f2 = __half22float2(hp[2]);
    float2 f3 = __half22float2(hp[3]);
    float4 p0, p1;
    p0.x = u * f0.x * v0.x;  p0.y = u * f0.y * v0.y;
    p0.z = u * f1.x * v0.z;  p0.w = u * f1.y * v0.w;
    p1.x = u * f2.x * v1.x;  p1.y = u * f2.y * v1.y;
    p1.z = u * f3.x * v1.z;  p1.w = u * f3.y * v1.w;
    float4* O4 = reinterpret_cast<float4*>(out);
    O4[2 * idx]     = p0;
    O4[2 * idx + 1] = p1;
}

// ---------------------------------------------------------------------------
extern "C" void kernel_launch(void* const* d_in, const int* in_sizes, int n_in,
                              void* d_out, int out_size) {
    const float* C = (const float*)d_in[0];
    const float* d = (const float*)d_in[1];
    const float* s = (const float*)d_in[2];
    float* out = (float*)d_out;

    cudaFuncSetAttribute(iter_kernel,
                         cudaFuncAttributeMaxDynamicSharedMemorySize, SM_TOTAL);

    const int VBLOCKS = (NN * NC4) / 256;    // 32768

    precompute_kernel<<<VBLOCKS, 256>>>(C);

    for (int it = 0; it < 50; ++it) {
        iter_kernel<<<NCTAS, NTHR, SM_TOTAL>>>(d);
        col_reduce_kernel<<<64, 256>>>(s);
    }

    final_kernel<<<VBLOCKS, 256>>>(out);
}

// round 9
// speedup vs baseline: 1.1087x; 1.1087x over previous
#include <cuda_runtime.h>
#include <cuda_fp16.h>
#include <cstdint>

// Sinkhorn-Knopp, fp16 matrix. ONE DRAM sweep per iteration (cp.async SMEM
// staging, 3-deep pipeline, thread-private buffer ownership), 2 CTAs/SM.
// R9: ONE barrier per 2-row group — warp partials published once, then every
// thread redundantly reduces (fixed order, deterministic) and computes eu
// itself (MUFU rcp). ev decode hoisted out of the group loop.
//   E' = 1024*exp(-10*C) fp16; global scale cancels exactly.
//   iter: per group: eu_r = (d_r+eps)/sum_j E_rj evh_j ; colacc_j += eu_r E_rj
//   col_reduce: ev_j = (s_j+eps)/sum_{cta} part[cta][j] (fixed order)
//   P = eu_i E'_ij ev_j

#define NN 8192
#define NC4 (NN / 8)                 // 1024 uint4 chunks (8 halves) per row
#define GROWS 2                      // rows per group (32 KB)
#define NGROUPS (NN / GROWS)         // 4096
#define NCTAS 296                    // 2 CTAs per SM
#define NTHR 512
#define EPS 1e-6f
#define ESCALE 1024.0f

// smem layout (bytes): 3 buffers x 2 rows x 1024 uint4 = 98304
#define SM_BUF   0
#define SM_WPART 98304               // float[2 parities][2 rows][16 warps]
#define SM_TOTAL 98560

__device__ __align__(16) __half g_E[(size_t)NN * NN];        // 128 MB
__device__ __align__(16) float  g_eu[NN];
__device__ __align__(16) float  g_ev[NN];                    // fp32 (final)
__device__ __align__(16) __half g_evh[NN];                   // fp16 (hot loop)
__device__ __align__(16) float  g_part[(size_t)NCTAS * NN];  // 9.7 MB

__device__ __forceinline__ void cpa16(uint32_t smem_dst, const void* gsrc) {
    asm volatile("cp.async.cg.shared.global [%0], [%1], 16;\n"
                 :: "r"(smem_dst), "l"(gsrc));
}
#define CP_COMMIT() asm volatile("cp.async.commit_group;\n" ::: "memory")
#define CP_WAIT2()  asm volatile("cp.async.wait_group 2;\n" ::: "memory")

// FMA-only exp for x in [-15, 0]
__device__ __forceinline__ float fast_exp_neg(float x) {
    const float LOG2E = 1.4426950408889634f;
    float t = x * LOG2E;
    float n = rintf(t);
    float f = t - n;
    float p = 1.5403530393381608e-4f;
    p = fmaf(p, f, 1.3333558146428443e-3f);
    p = fmaf(p, f, 9.6181291076284770e-3f);
    p = fmaf(p, f, 5.5504108664821580e-2f);
    p = fmaf(p, f, 2.4022650695910070e-1f);
    p = fmaf(p, f, 6.9314718055994530e-1f);
    p = fmaf(p, f, 1.0f);
    return p * __int_as_float(((int)n + 127) << 23);
}

// ---------------------------------------------------------------------------
__global__ void precompute_kernel(const float* __restrict__ C) {
    size_t g = (size_t)blockIdx.x * blockDim.x + threadIdx.x;
    const float4* C4 = reinterpret_cast<const float4*>(C);
    float4 c0 = C4[2 * g];
    float4 c1 = C4[2 * g + 1];
    __half2 h[4];
    h[0] = __floats2half2_rn(ESCALE * fast_exp_neg(-10.0f * c0.x),
                             ESCALE * fast_exp_neg(-10.0f * c0.y));
    h[1] = __floats2half2_rn(ESCALE * fast_exp_neg(-10.0f * c0.z),
                             ESCALE * fast_exp_neg(-10.0f * c0.w));
    h[2] = __floats2half2_rn(ESCALE * fast_exp_neg(-10.0f * c1.x),
                             ESCALE * fast_exp_neg(-10.0f * c1.y));
    h[3] = __floats2half2_rn(ESCALE * fast_exp_neg(-10.0f * c1.z),
                             ESCALE * fast_exp_neg(-10.0f * c1.w));
    reinterpret_cast<uint4*>(g_E)[g] = *reinterpret_cast<uint4*>(h);
    if (g < NN) {
        const float E1 = 2.718281828459045f;      // exp(v0), v0 = 1
        g_ev[g]  = E1;
        g_evh[g] = __float2half_rn(E1);
    }
}

// ---------------------------------------------------------------------------
// Fused iteration kernel: 296 CTAs x 512 threads, 2 CTAs/SM.
// CTA c handles 2-row groups {c, c+296, ...}. Thread t owns chunks t and
// t+512 of every row it touches. ONE barrier per group.
// ---------------------------------------------------------------------------
__global__ void __launch_bounds__(NTHR, 2)
iter_kernel(const float* __restrict__ d) {
    extern __shared__ char smraw[];
    uint4* buf   = reinterpret_cast<uint4*>(smraw + SM_BUF);   // [3][2][1024]
    float* wpart = reinterpret_cast<float*>(smraw + SM_WPART); // [2][2][16]

    const int tid  = threadIdx.x;
    const int wid  = tid >> 5;
    const int lane = tid & 31;
    const int cta  = blockIdx.x;
    const int ng   = (NGROUPS - cta + NCTAS - 1) / NCTAS;      // 13 or 14

    const uint4* Eg  = reinterpret_cast<const uint4*>(g_E);
    const uint4* EVH = reinterpret_cast<const uint4*>(g_evh);

    const uint32_t smbase = (uint32_t)__cvta_generic_to_shared(buf);

    auto prefetch = [&](int t) {
        const int grow0 = (cta + t * NCTAS) * GROWS;
        const uint32_t sb = smbase + (uint32_t)((t % 3) * 2048) * 16u;
#pragma unroll
        for (int r = 0; r < GROWS; ++r) {
            const uint4* src = Eg + (size_t)(grow0 + r) * NC4;
            cpa16(sb + (uint32_t)(r * 1024 + tid) * 16u,       src + tid);
            cpa16(sb + (uint32_t)(r * 1024 + tid + 512) * 16u, src + tid + 512);
        }
    };

    prefetch(0); CP_COMMIT();
    prefetch(1); CP_COMMIT();

    // hoisted ev decode (loop-invariant within one iteration)
    float va[8], vb[8];
    {
        uint4 ev = __ldg(EVH + tid);
        const __half2* hv = reinterpret_cast<const __half2*>(&ev);
#pragma unroll
        for (int k = 0; k < 4; ++k) {
            float2 v = __half22float2(hv[k]);
            va[2 * k] = v.x; va[2 * k + 1] = v.y;
        }
        ev = __ldg(EVH + tid + 512);
        hv = reinterpret_cast<const __half2*>(&ev);
#pragma unroll
        for (int k = 0; k < 4; ++k) {
            float2 v = __half22float2(hv[k]);
            vb[2 * k] = v.x; vb[2 * k + 1] = v.y;
        }
    }

    float ca[8] = {0.f, 0.f, 0.f, 0.f, 0.f, 0.f, 0.f, 0.f};   // cols, chunk tid
    float cb[8] = {0.f, 0.f, 0.f, 0.f, 0.f, 0.f, 0.f, 0.f};   // cols, chunk tid+512

    for (int t = 0; t < ng; ++t) {
        if (t + 2 < ng) prefetch(t + 2);
        CP_COMMIT();
        CP_WAIT2();                   // own copies of group t complete

        const uint4* B = buf + (t % 3) * 2048;
        const int grow0 = (cta + t * NCTAS) * GROWS;
        float* wp = wpart + (t & 1) * 32;         // parity-buffered partials

        // ---- phase 1: row partials (2 chunks x 2 rows per thread) ---------
        float rp0 = 0.f, rp1 = 0.f;
#pragma unroll
        for (int r = 0; r < GROWS; ++r) {
            uint4 eA = B[r * 1024 + tid];
            uint4 eB = B[r * 1024 + tid + 512];
            const __half2* ha = reinterpret_cast<const __half2*>(&eA);
            const __half2* hb = reinterpret_cast<const __half2*>(&eB);
            float acc = 0.f;
#pragma unroll
            for (int k = 0; k < 4; ++k) {
                float2 fa = __half22float2(ha[k]);
                float2 fb = __half22float2(hb[k]);
                acc = fmaf(fa.x, va[2 * k], acc);
                acc = fmaf(fa.y, va[2 * k + 1], acc);
                acc = fmaf(fb.x, vb[2 * k], acc);
                acc = fmaf(fb.y, vb[2 * k + 1], acc);
            }
            if (r == 0) rp0 = acc; else rp1 = acc;
        }
#pragma unroll
        for (int o = 16; o > 0; o >>= 1) {
            rp0 += __shfl_down_sync(0xFFFFFFFFu, rp0, o);
            rp1 += __shfl_down_sync(0xFFFFFFFFu, rp1, o);
        }
        if (lane == 0) {
            wp[wid]      = rp0;
            wp[16 + wid] = rp1;
        }
        __syncthreads();              // the ONLY barrier in the group

        // ---- redundant deterministic reduction (all threads, fixed order) -
        float eu0, eu1;
        {
            const float4* W4 = reinterpret_cast<const float4*>(wp);
            float4 q0 = W4[0], q1 = W4[1], q2 = W4[2], q3 = W4[3];
            float s0 = ((q0.x + q0.y) + (q0.z + q0.w))
                     + ((q1.x + q1.y) + (q1.z + q1.w))
                     + ((q2.x + q2.y) + (q2.z + q2.w))
                     + ((q3.x + q3.y) + (q3.z + q3.w));
            float4 r0 = W4[4], r1 = W4[5], r2 = W4[6], r3 = W4[7];
            float s1 = ((r0.x + r0.y) + (r0.z + r0.w))
                     + ((r1.x + r1.y) + (r1.z + r1.w))
                     + ((r2.x + r2.y) + (r2.z + r2.w))
                     + ((r3.x + r3.y) + (r3.z + r3.w));
            eu0 = (__ldg(d + grow0)     + EPS) * __frcp_rn(s0);
            eu1 = (__ldg(d + grow0 + 1) + EPS) * __frcp_rn(s1);
        }
        if (tid == 0) {               // for final_kernel
            g_eu[grow0]     = eu0;
            g_eu[grow0 + 1] = eu1;
        }

        // ---- phase 2: column accumulation (persistent registers) ----------
#pragma unroll
        for (int r = 0; r < GROWS; ++r) {
            float u = (r == 0) ? eu0 : eu1;
            uint4 eA = B[r * 1024 + tid];
            uint4 eB = B[r * 1024 + tid + 512];
            const __half2* ha = reinterpret_cast<const __half2*>(&eA);
            const __half2* hb = reinterpret_cast<const __half2*>(&eB);
#pragma unroll
            for (int k = 0; k < 4; ++k) {
                float2 fa = __half22float2(ha[k]);
                float2 fb = __half22float2(hb[k]);
                ca[2 * k]     = fmaf(fa.x, u, ca[2 * k]);
                ca[2 * k + 1] = fmaf(fa.y, u, ca[2 * k + 1]);
                cb[2 * k]     = fmaf(fb.x, u, cb[2 * k]);
                cb[2 * k + 1] = fmaf(fb.y, u, cb[2 * k + 1]);
            }
        }
        // no trailing barrier: thread-private buffer chunks + parity wpart
    }

    float4* P4 = reinterpret_cast<float4*>(g_part + (size_t)cta * NN);
    P4[2 * tid]             = make_float4(ca[0], ca[1], ca[2], ca[3]);
    P4[2 * tid + 1]         = make_float4(ca[4], ca[5], ca[6], ca[7]);
    P4[2 * (tid + 512)]     = make_float4(cb[0], cb[1], cb[2], cb[3]);
    P4[2 * (tid + 512) + 1] = make_float4(cb[4], cb[5], cb[6], cb[7]);
}

// ---------------------------------------------------------------------------
// ev_j = (s_j+eps) / sum over 296 CTA partials (fixed order, deterministic).
// grid = 64 CTAs x 256 threads; 8 slices x 37 partials; fixed-order combine.
// ---------------------------------------------------------------------------
__global__ void col_reduce_kernel(const float* __restrict__ s) {
    __shared__ float4 red[8][32];
    const int g     = threadIdx.x & 31;
    const int slice = threadIdx.x >> 5;          // 0..7
    const int col4  = blockIdx.x * 32 + g;       // 0..2047
    const float4* P4 = reinterpret_cast<const float4*>(g_part);
    float4 acc = make_float4(0.f, 0.f, 0.f, 0.f);
#pragma unroll
    for (int k = 0; k < 37; ++k) {
        float4 v = P4[(size_t)(slice * 37 + k) * (NN / 4) + col4];
        acc.x += v.x; acc.y += v.y; acc.z += v.z; acc.w += v.w;
    }
    red[slice][g] = acc;
    __syncthreads();
    if (slice == 0) {
        float4 t = red[0][g];
#pragma unroll
        for (int q = 1; q < 8; ++q) {            // fixed order
            float4 r = red[q][g];
            t.x += r.x; t.y += r.y; t.z += r.z; t.w += r.w;
        }
        int j0 = col4 * 4;
        float e0 = (s[j0 + 0] + EPS) / t.x;
        float e1 = (s[j0 + 1] + EPS) / t.y;
        float e2 = (s[j0 + 2] + EPS) / t.z;
        float e3 = (s[j0 + 3] + EPS) / t.w;
        reinterpret_cast<float4*>(g_ev)[col4] = make_float4(e0, e1, e2, e3);
        __half2* VH2 = reinterpret_cast<__half2*>(g_evh);
        VH2[2 * col4]     = __floats2half2_rn(e0, e1);
        VH2[2 * col4 + 1] = __floats2half2_rn(e2, e3);
    }
}

// ---------------------------------------------------------------------------
// Final: P_ij = eu_i * E'_ij * ev_j   (fp32 eu/ev)
// ---------------------------------------------------------------------------
__global__ void final_kernel(float* __restrict__ out) {
    size_t idx = (size_t)blockIdx.x * blockDim.x + threadIdx.x;
    int row = (int)(idx / NC4);
    int c8  = (int)(idx % NC4);
    float u = g_eu[row];
    const float4* ev4 = reinterpret_cast<const float4*>(g_ev);
    float4 v0 = ev4[2 * c8];
    float4 v1 = ev4[2 * c8 + 1];
    uint4 e = reinterpret_cast<const uint4*>(g_E)[idx];
    const __half2* hp = reinterpret_cast<const __half2*>(&e);
    float2 f0 = __half22float2(hp[0]);
    float2 f1 = __half22float2(hp[1]);
    float2 f2 = __half22float2(hp[2]);
    float2 f3 = __half22float2(hp[3]);
    float4 p0, p1;
    p0.x = u * f0.x * v0.x;  p0.y = u * f0.y * v0.y;
    p0.z = u * f1.x * v0.z;  p0.w = u * f1.y * v0.w;
    p1.x = u * f2.x * v1.x;  p1.y = u * f2.y * v1.y;
    p1.z = u * f3.x * v1.z;  p1.w = u * f3.y * v1.w;
    float4* O4 = reinterpret_cast<float4*>(out);
    O4[2 * idx]     = p0;
    O4[2 * idx + 1] = p1;
}

// ---------------------------------------------------------------------------
extern "C" void kernel_launch(void* const* d_in, const int* in_sizes, int n_in,
                              void* d_out, int out_size) {
    const float* C = (const float*)d_in[0];
    const float* d = (const float*)d_in[1];
    const float* s = (const float*)d_in[2];
    float* out = (float*)d_out;

    cudaFuncSetAttribute(iter_kernel,
                         cudaFuncAttributeMaxDynamicSharedMemorySize, SM_TOTAL);

    const int VBLOCKS = (NN * NC4) / 256;    // 32768

    precompute_kernel<<<VBLOCKS, 256>>>(C);

    for (int it = 0; it < 50; ++it) {
        iter_kernel<<<NCTAS, NTHR, SM_TOTAL>>>(d);
        col_reduce_kernel<<<64, 256>>>(s);
    }

    final_kernel<<<VBLOCKS, 256>>>(out);
}

// round 10
// speedup vs baseline: 1.1873x; 1.0708x over previous
#include <cuda_runtime.h>
#include <cuda_fp16.h>
#include <cstdint>

// Sinkhorn-Knopp, fp16 matrix, ONE DRAM sweep/iter (cp.async 3-deep pipeline,
// thread-private chunks, 2 CTAs/SM, 1 barrier/group). R10: hot math entirely
// in HFMA2 — E' is never converted to fp32 in the hot loop.
// Scales: E' = 1024*exp(-10*C) (fp16), evh = ev/32 (fp16), uh = eu_true.
//   phase1: rp_h2 += E' * evh  -> rowsum*32; eu_t = 32(d+eps)/rs
//   phase2: cacc_h2 += eu_t * E'  (fp16 partial colsums, 28-term chains)
//   col_reduce: colsum = sum(partials)/1; ev = (s+eps)*1024/sum; evh = ev/32
//   final: P = (eu_t/1024) * E' * ev   == eu*E*ev exactly (powers of 2)

#define NN 8192
#define NC4 (NN / 8)                 // 1024 uint4 chunks per row
#define GROWS 2
#define NGROUPS (NN / GROWS)         // 4096
#define NCTAS 296
#define NTHR 512
#define EPS 1e-6f
#define ESCALE 1024.0f

#define SM_BUF   0                   // 3 x 2 x 1024 uint4 = 98304 B
#define SM_WPART 98304               // float[2][32]
#define SM_TOTAL 98560

__device__ __align__(16) __half g_E[(size_t)NN * NN];          // 128 MB
__device__ __align__(16) float  g_eu[NN];                      // eu' (for final)
__device__ __align__(16) float  g_ev[NN];                      // fp32 ev (final)
__device__ __align__(16) __half g_evh[NN];                     // ev/32 (hot loop)
__device__ __align__(16) __half g_parth[(size_t)NCTAS * NN];   // 4.85 MB fp16

__device__ __forceinline__ void cpa16(uint32_t smem_dst, const void* gsrc) {
    asm volatile("cp.async.cg.shared.global [%0], [%1], 16;\n"
                 :: "r"(smem_dst), "l"(gsrc));
}
#define CP_COMMIT() asm volatile("cp.async.commit_group;\n" ::: "memory")
#define CP_WAIT2()  asm volatile("cp.async.wait_group 2;\n" ::: "memory")

// FMA-only exp for x in [-15, 0]
__device__ __forceinline__ float fast_exp_neg(float x) {
    const float LOG2E = 1.4426950408889634f;
    float t = x * LOG2E;
    float n = rintf(t);
    float f = t - n;
    float p = 1.5403530393381608e-4f;
    p = fmaf(p, f, 1.3333558146428443e-3f);
    p = fmaf(p, f, 9.6181291076284770e-3f);
    p = fmaf(p, f, 5.5504108664821580e-2f);
    p = fmaf(p, f, 2.4022650695910070e-1f);
    p = fmaf(p, f, 6.9314718055994530e-1f);
    p = fmaf(p, f, 1.0f);
    return p * __int_as_float(((int)n + 127) << 23);
}

// ---------------------------------------------------------------------------
__global__ void precompute_kernel(const float* __restrict__ C) {
    size_t g = (size_t)blockIdx.x * blockDim.x + threadIdx.x;
    const float4* C4 = reinterpret_cast<const float4*>(C);
    float4 c0 = C4[2 * g];
    float4 c1 = C4[2 * g + 1];
    __half2 h[4];
    h[0] = __floats2half2_rn(ESCALE * fast_exp_neg(-10.0f * c0.x),
                             ESCALE * fast_exp_neg(-10.0f * c0.y));
    h[1] = __floats2half2_rn(ESCALE * fast_exp_neg(-10.0f * c0.z),
                             ESCALE * fast_exp_neg(-10.0f * c0.w));
    h[2] = __floats2half2_rn(ESCALE * fast_exp_neg(-10.0f * c1.x),
                             ESCALE * fast_exp_neg(-10.0f * c1.y));
    h[3] = __floats2half2_rn(ESCALE * fast_exp_neg(-10.0f * c1.z),
                             ESCALE * fast_exp_neg(-10.0f * c1.w));
    reinterpret_cast<uint4*>(g_E)[g] = *reinterpret_cast<uint4*>(h);
    if (g < NN) {
        const float E1 = 2.718281828459045f;      // exp(v0), v0 = 1
        g_ev[g]  = E1;
        g_evh[g] = __float2half_rn(E1 * 0.03125f);  // ev/32
    }
}

// ---------------------------------------------------------------------------
// Fused iteration: 296 CTAs x 512 threads, 2 CTAs/SM. Thread t owns chunks
// t and t+512. HFMA2 throughout; E chunks stay in registers across phases.
// ---------------------------------------------------------------------------
__global__ void __launch_bounds__(NTHR, 2)
iter_kernel(const float* __restrict__ d) {
    extern __shared__ char smraw[];
    uint4* buf   = reinterpret_cast<uint4*>(smraw + SM_BUF);   // [3][2][1024]
    float* wpart = reinterpret_cast<float*>(smraw + SM_WPART); // [2][32]

    const int tid  = threadIdx.x;
    const int wid  = tid >> 5;
    const int lane = tid & 31;
    const int cta  = blockIdx.x;
    const int ng   = (NGROUPS - cta + NCTAS - 1) / NCTAS;      // 13 or 14

    const uint4* Eg  = reinterpret_cast<const uint4*>(g_E);
    const uint4* EVH = reinterpret_cast<const uint4*>(g_evh);

    const uint32_t smbase = (uint32_t)__cvta_generic_to_shared(buf);

    auto prefetch = [&](int t) {
        const int grow0 = (cta + t * NCTAS) * GROWS;
        const uint32_t sb = smbase + (uint32_t)((t % 3) * 2048) * 16u;
#pragma unroll
        for (int r = 0; r < GROWS; ++r) {
            const uint4* src = Eg + (size_t)(grow0 + r) * NC4;
            cpa16(sb + (uint32_t)(r * 1024 + tid) * 16u,       src + tid);
            cpa16(sb + (uint32_t)(r * 1024 + tid + 512) * 16u, src + tid + 512);
        }
    };

    prefetch(0); CP_COMMIT();
    prefetch(1); CP_COMMIT();

    // ev/32 for this thread's 16 columns, kept as 8 half2 regs
    __half2 va2[4], vb2[4];
    {
        uint4 v = __ldg(EVH + tid);
        const __half2* hv = reinterpret_cast<const __half2*>(&v);
#pragma unroll
        for (int k = 0; k < 4; ++k) va2[k] = hv[k];
        v = __ldg(EVH + tid + 512);
        hv = reinterpret_cast<const __half2*>(&v);
#pragma unroll
        for (int k = 0; k < 4; ++k) vb2[k] = hv[k];
    }

    __half2 cacc[8];
#pragma unroll
    for (int k = 0; k < 8; ++k) cacc[k] = __float2half2_rn(0.0f);

    for (int t = 0; t < ng; ++t) {
        if (t + 2 < ng) prefetch(t + 2);
        CP_COMMIT();
        CP_WAIT2();

        const uint4* B = buf + (t % 3) * 2048;
        const int grow0 = (cta + t * NCTAS) * GROWS;
        float* wp = wpart + (t & 1) * 32;

        // load the 4 owned chunks once; reuse in both phases
        uint4 eA0 = B[tid];
        uint4 eB0 = B[tid + 512];
        uint4 eA1 = B[1024 + tid];
        uint4 eB1 = B[1024 + tid + 512];
        const __half2* a0 = reinterpret_cast<const __half2*>(&eA0);
        const __half2* b0 = reinterpret_cast<const __half2*>(&eB0);
        const __half2* a1 = reinterpret_cast<const __half2*>(&eA1);
        const __half2* b1 = reinterpret_cast<const __half2*>(&eB1);

        // ---- phase 1: rowsum partials in HFMA2 ----------------------------
        __half2 rp0 = __float2half2_rn(0.0f);
        __half2 rp1 = __float2half2_rn(0.0f);
#pragma unroll
        for (int k = 0; k < 4; ++k) {
            rp0 = __hfma2(a0[k], va2[k], rp0);
            rp0 = __hfma2(b0[k], vb2[k], rp0);
            rp1 = __hfma2(a1[k], va2[k], rp1);
            rp1 = __hfma2(b1[k], vb2[k], rp1);
        }
        float2 f0 = __half22float2(rp0);
        float2 f1 = __half22float2(rp1);
        float s0 = f0.x + f0.y;
        float s1 = f1.x + f1.y;
#pragma unroll
        for (int o = 16; o > 0; o >>= 1) {
            s0 += __shfl_down_sync(0xFFFFFFFFu, s0, o);
            s1 += __shfl_down_sync(0xFFFFFFFFu, s1, o);
        }
        if (lane == 0) {
            wp[wid]      = s0;
            wp[16 + wid] = s1;
        }
        __syncthreads();              // the only barrier in the group

        // ---- redundant deterministic reduce + eu (all threads) ------------
        float eu0, eu1;
        {
            const float4* W4 = reinterpret_cast<const float4*>(wp);
            float4 q0 = W4[0], q1 = W4[1], q2 = W4[2], q3 = W4[3];
            float rs0 = ((q0.x + q0.y) + (q0.z + q0.w))
                      + ((q1.x + q1.y) + (q1.z + q1.w))
                      + ((q2.x + q2.y) + (q2.z + q2.w))
                      + ((q3.x + q3.y) + (q3.z + q3.w));
            float4 r0 = W4[4], r1 = W4[5], r2 = W4[6], r3 = W4[7];
            float rs1 = ((r0.x + r0.y) + (r0.z + r0.w))
                      + ((r1.x + r1.y) + (r1.z + r1.w))
                      + ((r2.x + r2.y) + (r2.z + r2.w))
                      + ((r3.x + r3.y) + (r3.z + r3.w));
            // rs = 32*1024*rowsum_true ; eu_t = 32(d+eps)/rs = eu_true
            eu0 = __fdividef((__ldg(d + grow0)     + EPS) * 32.0f, rs0);
            eu1 = __fdividef((__ldg(d + grow0 + 1) + EPS) * 32.0f, rs1);
        }
        if (tid == 0) {               // eu' = eu_true/1024 for final kernel
            g_eu[grow0]     = eu0 * (1.0f / 1024.0f);
            g_eu[grow0 + 1] = eu1 * (1.0f / 1024.0f);
        }

        // ---- phase 2: fp16 column accumulation ----------------------------
        __half2 u0 = __float2half2_rn(eu0);
        __half2 u1 = __float2half2_rn(eu1);
#pragma unroll
        for (int k = 0; k < 4; ++k) {
            cacc[k]     = __hfma2(a0[k], u0, cacc[k]);
            cacc[4 + k] = __hfma2(b0[k], u0, cacc[4 + k]);
            cacc[k]     = __hfma2(a1[k], u1, cacc[k]);
            cacc[4 + k] = __hfma2(b1[k], u1, cacc[4 + k]);
        }
    }

    // write fp16 partials: chunk tid -> halves [8*tid, 8*tid+8)
    uint4* PH = reinterpret_cast<uint4*>(g_parth + (size_t)cta * NN);
    uint4 o0, o1;
    __half2* p0 = reinterpret_cast<__half2*>(&o0);
    __half2* p1 = reinterpret_cast<__half2*>(&o1);
#pragma unroll
    for (int k = 0; k < 4; ++k) { p0[k] = cacc[k]; p1[k] = cacc[4 + k]; }
    PH[tid]       = o0;
    PH[tid + 512] = o1;
}

// ---------------------------------------------------------------------------
// ev from fp16 partials: colsum_scaled = sum_{296} partial (fp32, fixed order)
// = 1024*colsum_true ; ev = (s+eps)*1024/colsum_scaled ; evh = ev/32.
// grid = 32 CTAs x 256 threads; thread (slice 0..7, chunk 0..31).
// ---------------------------------------------------------------------------
__global__ void col_reduce_kernel(const float* __restrict__ s) {
    __shared__ float red[8][32][8];
    const int g     = threadIdx.x & 31;
    const int slice = threadIdx.x >> 5;
    const int chunk = blockIdx.x * 32 + g;       // 0..1023 (8 cols each)
    const uint4* PH = reinterpret_cast<const uint4*>(g_parth);
    float acc[8] = {0.f, 0.f, 0.f, 0.f, 0.f, 0.f, 0.f, 0.f};
#pragma unroll
    for (int k = 0; k < 37; ++k) {
        uint4 v = PH[(size_t)(slice * 37 + k) * NC4 + chunk];
        const __half2* h = reinterpret_cast<const __half2*>(&v);
#pragma unroll
        for (int m = 0; m < 4; ++m) {
            float2 f = __half22float2(h[m]);
            acc[2 * m]     += f.x;
            acc[2 * m + 1] += f.y;
        }
    }
#pragma unroll
    for (int m = 0; m < 8; ++m) red[slice][g][m] = acc[m];
    __syncthreads();
    if (slice == 0) {
        float t[8];
#pragma unroll
        for (int m = 0; m < 8; ++m) t[m] = red[0][g][m];
#pragma unroll
        for (int q = 1; q < 8; ++q)                 // fixed order
#pragma unroll
            for (int m = 0; m < 8; ++m) t[m] += red[q][g][m];
        const int j0 = chunk * 8;
        float ev[8];
#pragma unroll
        for (int m = 0; m < 8; ++m)
            ev[m] = (s[j0 + m] + EPS) * 1024.0f / t[m];
        float4* EV4 = reinterpret_cast<float4*>(g_ev + j0);
        EV4[0] = make_float4(ev[0], ev[1], ev[2], ev[3]);
        EV4[1] = make_float4(ev[4], ev[5], ev[6], ev[7]);
        uint4 hv;
        __half2* hp = reinterpret_cast<__half2*>(&hv);
#pragma unroll
        for (int m = 0; m < 4; ++m)
            hp[m] = __floats2half2_rn(ev[2 * m] * 0.03125f,
                                      ev[2 * m + 1] * 0.03125f);
        *reinterpret_cast<uint4*>(g_evh + j0) = hv;
    }
}

// ---------------------------------------------------------------------------
// Final: P_ij = eu'_i * E'_ij * ev_j   (fp32 eu'/ev)
// ---------------------------------------------------------------------------
__global__ void final_kernel(float* __restrict__ out) {
    size_t idx = (size_t)blockIdx.x * blockDim.x + threadIdx.x;
    int row = (int)(idx / NC4);
    int c8  = (int)(idx % NC4);
    float u = g_eu[row];
    const float4* ev4 = reinterpret_cast<const float4*>(g_ev);
    float4 v0 = ev4[2 * c8];
    float4 v1 = ev4[2 * c8 + 1];
    uint4 e = reinterpret_cast<const uint4*>(g_E)[idx];
    const __half2* hp = reinterpret_cast<const __half2*>(&e);
    float2 f0 = __half22float2(hp[0]);
    float2 f1 = __half22float2(hp[1]);
    float2 f2 = __half22float2(hp[2]);
    float2 f3 = __half22float2(hp[3]);
    float4 p0, p1;
    p0.x = u * f0.x * v0.x;  p0.y = u * f0.y * v0.y;
    p0.z = u * f1.x * v0.z;  p0.w = u * f1.y * v0.w;
    p1.x = u * f2.x * v1.x;  p1.y = u * f2.y * v1.y;
    p1.z = u * f3.x * v1.z;  p1.w = u * f3.y * v1.w;
    float4* O4 = reinterpret_cast<float4*>(out);
    O4[2 * idx]     = p0;
    O4[2 * idx + 1] = p1;
}

// ---------------------------------------------------------------------------
extern "C" void kernel_launch(void* const* d_in, const int* in_sizes, int n_in,
                              void* d_out, int out_size) {
    const float* C = (const float*)d_in[0];
    const float* d = (const float*)d_in[1];
    const float* s = (const float*)d_in[2];
    float* out = (float*)d_out;

    cudaFuncSetAttribute(iter_kernel,
                         cudaFuncAttributeMaxDynamicSharedMemorySize, SM_TOTAL);

    const int VBLOCKS = (NN * NC4) / 256;    // 32768

    precompute_kernel<<<VBLOCKS, 256>>>(C);

    for (int it = 0; it < 50; ++it) {
        iter_kernel<<<NCTAS, NTHR, SM_TOTAL>>>(d);
        col_reduce_kernel<<<32, 256>>>(s);
    }

    final_kernel<<<VBLOCKS, 256>>>(out);
}

// round 11
// speedup vs baseline: 1.3453x; 1.1331x over previous
#include <cuda_runtime.h>
#include <cuda_fp16.h>
#include <cstdint>

// Sinkhorn-Knopp, fp16 matrix, ONE DRAM sweep/iter. R11: NO smem staging —
// E goes DRAM -> registers via __ldcs LDG.128, double-buffered across 2-row
// groups; both phases consume the same registers. Block reduction via smem
// publish + xor-butterfly (fixed tree, deterministic). 1 barrier per group.
// Scales: E' = 1024*exp(-10*C) (fp16), evh = ev/32 (fp16).
//   phase1: rp_h2 += E' * evh  -> 32*rowsum; eu = 32(d+eps)/rs
//   phase2: cacc_h2 += eu * E'  (fp16 partial colsums)
//   col_reduce: ev = (s+eps)*1024/sum(partials); evh = ev/32
//   final: P = (eu/1024) * E' * ev  == eu*E*ev exactly (powers of 2)

#define NN 8192
#define NC4 (NN / 8)                 // 1024 uint4 chunks per row
#define GROWS 2
#define NGROUPS (NN / GROWS)         // 4096
#define NCTAS 296                    // 2 CTAs/SM
#define NTHR 512
#define EPS 1e-6f
#define ESCALE 1024.0f

__device__ __align__(16) __half g_E[(size_t)NN * NN];          // 128 MB
__device__ __align__(16) float  g_eu[NN];                      // eu/1024 (final)
__device__ __align__(16) float  g_ev[NN];                      // fp32 ev (final)
__device__ __align__(16) __half g_evh[NN];                     // ev/32 (hot loop)
__device__ __align__(16) __half g_parth[(size_t)NCTAS * NN];   // 4.85 MB fp16

// FMA-only exp for x in [-15, 0]
__device__ __forceinline__ float fast_exp_neg(float x) {
    const float LOG2E = 1.4426950408889634f;
    float t = x * LOG2E;
    float n = rintf(t);
    float f = t - n;
    float p = 1.5403530393381608e-4f;
    p = fmaf(p, f, 1.3333558146428443e-3f);
    p = fmaf(p, f, 9.6181291076284770e-3f);
    p = fmaf(p, f, 5.5504108664821580e-2f);
    p = fmaf(p, f, 2.4022650695910070e-1f);
    p = fmaf(p, f, 6.9314718055994530e-1f);
    p = fmaf(p, f, 1.0f);
    return p * __int_as_float(((int)n + 127) << 23);
}

// ---------------------------------------------------------------------------
__global__ void precompute_kernel(const float* __restrict__ C) {
    size_t g = (size_t)blockIdx.x * blockDim.x + threadIdx.x;
    const float4* C4 = reinterpret_cast<const float4*>(C);
    float4 c0 = C4[2 * g];
    float4 c1 = C4[2 * g + 1];
    __half2 h[4];
    h[0] = __floats2half2_rn(ESCALE * fast_exp_neg(-10.0f * c0.x),
                             ESCALE * fast_exp_neg(-10.0f * c0.y));
    h[1] = __floats2half2_rn(ESCALE * fast_exp_neg(-10.0f * c0.z),
                             ESCALE * fast_exp_neg(-10.0f * c0.w));
    h[2] = __floats2half2_rn(ESCALE * fast_exp_neg(-10.0f * c1.x),
                             ESCALE * fast_exp_neg(-10.0f * c1.y));
    h[3] = __floats2half2_rn(ESCALE * fast_exp_neg(-10.0f * c1.z),
                             ESCALE * fast_exp_neg(-10.0f * c1.w));
    reinterpret_cast<uint4*>(g_E)[g] = *reinterpret_cast<uint4*>(h);
    if (g < NN) {
        const float E1 = 2.718281828459045f;        // exp(v0), v0 = 1
        g_ev[g]  = E1;
        g_evh[g] = __float2half_rn(E1 * 0.03125f);  // ev/32
    }
}

// ---------------------------------------------------------------------------
// Fused iteration: 296 CTAs x 512 threads, 2 CTAs/SM, NO staging smem.
// Thread t owns chunks t and t+512 of each row. Register double buffer.
// ---------------------------------------------------------------------------
__global__ void __launch_bounds__(NTHR, 2)
iter_kernel(const float* __restrict__ d) {
    __shared__ float wpart[64];       // [2 parities][32]

    const int tid  = threadIdx.x;
    const int wid  = tid >> 5;
    const int lane = tid & 31;
    const int cta  = blockIdx.x;
    const int ng   = (NGROUPS - cta + NCTAS - 1) / NCTAS;      // 13 or 14

    const uint4* Eg  = reinterpret_cast<const uint4*>(g_E);
    const uint4* EVH = reinterpret_cast<const uint4*>(g_evh);

    // ev/32 for this thread's 16 columns (8 half2 regs, loop-invariant)
    __half2 va2[4], vb2[4];
    {
        uint4 v = __ldg(EVH + tid);
        const __half2* hv = reinterpret_cast<const __half2*>(&v);
#pragma unroll
        for (int k = 0; k < 4; ++k) va2[k] = hv[k];
        v = __ldg(EVH + tid + 512);
        hv = reinterpret_cast<const __half2*>(&v);
#pragma unroll
        for (int k = 0; k < 4; ++k) vb2[k] = hv[k];
    }

    __half2 cacc[8];
#pragma unroll
    for (int k = 0; k < 8; ++k) cacc[k] = __float2half2_rn(0.0f);

    // register double buffer: set A (even groups), set B (odd groups)
    uint4 xA0, xB0, xA1, xB1;         // current/even
    uint4 yA0, yB0, yA1, yB1;         // next/odd

    auto loadg = [&](int t, uint4& a0, uint4& b0, uint4& a1, uint4& b1) {
        const int grow0 = (cta + t * NCTAS) * GROWS;
        const uint4* s0 = Eg + (size_t)grow0 * NC4;
        const uint4* s1 = Eg + (size_t)(grow0 + 1) * NC4;
        a0 = __ldcs(s0 + tid);
        b0 = __ldcs(s0 + tid + 512);
        a1 = __ldcs(s1 + tid);
        b1 = __ldcs(s1 + tid + 512);
    };

    auto process = [&](int t, const uint4& eA0, const uint4& eB0,
                              const uint4& eA1, const uint4& eB1) {
        const int grow0 = (cta + t * NCTAS) * GROWS;
        float* wp = wpart + (t & 1) * 32;
        const __half2* a0 = reinterpret_cast<const __half2*>(&eA0);
        const __half2* b0 = reinterpret_cast<const __half2*>(&eB0);
        const __half2* a1 = reinterpret_cast<const __half2*>(&eA1);
        const __half2* b1 = reinterpret_cast<const __half2*>(&eB1);

        // ---- phase 1: rowsum partials in HFMA2 ----------------------------
        __half2 rp0 = __float2half2_rn(0.0f);
        __half2 rp1 = __float2half2_rn(0.0f);
#pragma unroll
        for (int k = 0; k < 4; ++k) {
            rp0 = __hfma2(a0[k], va2[k], rp0);
            rp0 = __hfma2(b0[k], vb2[k], rp0);
            rp1 = __hfma2(a1[k], va2[k], rp1);
            rp1 = __hfma2(b1[k], vb2[k], rp1);
        }
        float2 f0 = __half22float2(rp0);
        float2 f1 = __half22float2(rp1);
        float s0 = f0.x + f0.y;
        float s1 = f1.x + f1.y;
#pragma unroll
        for (int o = 16; o > 0; o >>= 1) {
            s0 += __shfl_down_sync(0xFFFFFFFFu, s0, o);
            s1 += __shfl_down_sync(0xFFFFFFFFu, s1, o);
        }
        if (lane == 0) {
            wp[wid]      = s0;
            wp[16 + wid] = s1;
        }
        __syncthreads();              // the only barrier in the group

        // ---- xor-butterfly over the 32 warp partials (fixed tree) ---------
        float v = wp[lane];           // lanes 0-15: row0, 16-31: row1
#pragma unroll
        for (int o = 1; o < 16; o <<= 1)
            v += __shfl_xor_sync(0xFFFFFFFFu, v, o);
        float w = __shfl_xor_sync(0xFFFFFFFFu, v, 16);
        float rs0 = (lane < 16) ? v : w;
        float rs1 = (lane < 16) ? w : v;
        // rs = 32*1024*rowsum_true ; eu = 32(d+eps)/rs = eu_true
        float eu0 = __fdividef((__ldg(d + grow0)     + EPS) * 32.0f, rs0);
        float eu1 = __fdividef((__ldg(d + grow0 + 1) + EPS) * 32.0f, rs1);
        if (tid == 0) {               // eu/1024 for final kernel
            g_eu[grow0]     = eu0 * (1.0f / 1024.0f);
            g_eu[grow0 + 1] = eu1 * (1.0f / 1024.0f);
        }

        // ---- phase 2: fp16 column accumulation ----------------------------
        __half2 u0 = __float2half2_rn(eu0);
        __half2 u1 = __float2half2_rn(eu1);
#pragma unroll
        for (int k = 0; k < 4; ++k) {
            cacc[k]     = __hfma2(a0[k], u0, cacc[k]);
            cacc[4 + k] = __hfma2(b0[k], u0, cacc[4 + k]);
            cacc[k]     = __hfma2(a1[k], u1, cacc[k]);
            cacc[4 + k] = __hfma2(b1[k], u1, cacc[4 + k]);
        }
    };

    loadg(0, xA0, xB0, xA1, xB1);
    for (int t = 0; t < ng; t += 2) {
        if (t + 1 < ng) loadg(t + 1, yA0, yB0, yA1, yB1);
        process(t, xA0, xB0, xA1, xB1);
        if (t + 1 < ng) {
            if (t + 2 < ng) loadg(t + 2, xA0, xB0, xA1, xB1);
            process(t + 1, yA0, yB0, yA1, yB1);
        }
    }

    // write fp16 partials: chunk tid -> halves [8*tid, 8*tid+8)
    uint4* PH = reinterpret_cast<uint4*>(g_parth + (size_t)cta * NN);
    uint4 o0, o1;
    __half2* p0 = reinterpret_cast<__half2*>(&o0);
    __half2* p1 = reinterpret_cast<__half2*>(&o1);
#pragma unroll
    for (int k = 0; k < 4; ++k) { p0[k] = cacc[k]; p1[k] = cacc[4 + k]; }
    PH[tid]       = o0;
    PH[tid + 512] = o1;
}

// ---------------------------------------------------------------------------
// ev from fp16 partials: sum 296 partials in fp32, fixed order.
// grid = 32 CTAs x 256 threads; thread (slice 0..7, chunk 0..31).
// ---------------------------------------------------------------------------
__global__ void col_reduce_kernel(const float* __restrict__ s) {
    __shared__ float red[8][32][8];
    const int g     = threadIdx.x & 31;
    const int slice = threadIdx.x >> 5;
    const int chunk = blockIdx.x * 32 + g;       // 0..1023 (8 cols each)
    const uint4* PH = reinterpret_cast<const uint4*>(g_parth);
    float acc[8] = {0.f, 0.f, 0.f, 0.f, 0.f, 0.f, 0.f, 0.f};
#pragma unroll
    for (int k = 0; k < 37; ++k) {
        uint4 v = PH[(size_t)(slice * 37 + k) * NC4 + chunk];
        const __half2* h = reinterpret_cast<const __half2*>(&v);
#pragma unroll
        for (int m = 0; m < 4; ++m) {
            float2 f = __half22float2(h[m]);
            acc[2 * m]     += f.x;
            acc[2 * m + 1] += f.y;
        }
    }
#pragma unroll
    for (int m = 0; m < 8; ++m) red[slice][g][m] = acc[m];
    __syncthreads();
    if (slice == 0) {
        float t[8];
#pragma unroll
        for (int m = 0; m < 8; ++m) t[m] = red[0][g][m];
#pragma unroll
        for (int q = 1; q < 8; ++q)                 // fixed order
#pragma unroll
            for (int m = 0; m < 8; ++m) t[m] += red[q][g][m];
        const int j0 = chunk * 8;
        float ev[8];
#pragma unroll
        for (int m = 0; m < 8; ++m)
            ev[m] = (s[j0 + m] + EPS) * 1024.0f / t[m];
        float4* EV4 = reinterpret_cast<float4*>(g_ev + j0);
        EV4[0] = make_float4(ev[0], ev[1], ev[2], ev[3]);
        EV4[1] = make_float4(ev[4], ev[5], ev[6], ev[7]);
        uint4 hv;
        __half2* hp = reinterpret_cast<__half2*>(&hv);
#pragma unroll
        for (int m = 0; m < 4; ++m)
            hp[m] = __floats2half2_rn(ev[2 * m] * 0.03125f,
                                      ev[2 * m + 1] * 0.03125f);
        *reinterpret_cast<uint4*>(g_evh + j0) = hv;
    }
}

// ---------------------------------------------------------------------------
// Final: P_ij = (eu_i/1024) * E'_ij * ev_j   (fp32 eu/ev)
// ---------------------------------------------------------------------------
__global__ void final_kernel(float* __restrict__ out) {
    size_t idx = (size_t)blockIdx.x * blockDim.x + threadIdx.x;
    int row = (int)(idx / NC4);
    int c8  = (int)(idx % NC4);
    float u = g_eu[row];
    const float4* ev4 = reinterpret_cast<const float4*>(g_ev);
    float4 v0 = ev4[2 * c8];
    float4 v1 = ev4[2 * c8 + 1];
    uint4 e = reinterpret_cast<const uint4*>(g_E)[idx];
    const __half2* hp = reinterpret_cast<const __half2*>(&e);
    float2 f0 = __half22float2(hp[0]);
    float2 f1 = __half22float2(hp[1]);
    float2 f2 = __half22float2(hp[2]);
    float2 f3 = __half22float2(hp[3]);
    float4 p0, p1;
    p0.x = u * f0.x * v0.x;  p0.y = u * f0.y * v0.y;
    p0.z = u * f1.x * v0.z;  p0.w = u * f1.y * v0.w;
    p1.x = u * f2.x * v1.x;  p1.y = u * f2.y * v1.y;
    p1.z = u * f3.x * v1.z;  p1.w = u * f3.y * v1.w;
    float4* O4 = reinterpret_cast<float4*>(out);
    O4[2 * idx]     = p0;
    O4[2 * idx + 1] = p1;
}

// ---------------------------------------------------------------------------
extern "C" void kernel_launch(void* const* d_in, const int* in_sizes, int n_in,
                              void* d_out, int out_size) {
    const float* C = (const float*)d_in[0];
    const float* d = (const float*)d_in[1];
    const float* s = (const float*)d_in[2];
    float* out = (float*)d_out;

    const int VBLOCKS = (NN * NC4) / 256;    // 32768

    precompute_kernel<<<VBLOCKS, 256>>>(C);

    for (int it = 0; it < 50; ++it) {
        iter_kernel<<<NCTAS, NTHR>>>(d);
        col_reduce_kernel<<<32, 256>>>(s);
    }

    final_kernel<<<VBLOCKS, 256>>>(out);
}

// round 13
// speedup vs baseline: 1.3785x; 1.0246x over previous
#include <cuda_runtime.h>
#include <cuda_fp16.h>
#include <cstdint>

// Sinkhorn-Knopp, fp16 matrix, ONE sweep/iter, register double-buffered LDG.
// R13 = R11 + L2 evict_last cache hints on rows [0, PERSIST_ROWS) (no
// device-limit call — that broke graph capture in R12; hints alone are
// architectural no-ops at worst).
//   E' = 1024*exp(-10*C) fp16, evh = ev/32 fp16.
//   phase1: rp_h2 += E'*evh -> 32*rowsum; eu = 32(d+eps)/rs
//   phase2: cacc_h2 += eu*E' (fp16 partial colsums)
//   col_reduce: ev = (s+eps)*1024/sum(partials); evh = ev/32
//   final: P = (eu/1024)*E'*ev == eu*E*ev exactly (powers of 2)

#define NN 8192
#define NC4 (NN / 8)                 // 1024 uint4 chunks per row
#define GROWS 2
#define NGROUPS (NN / GROWS)         // 4096
#define NCTAS 296                    // 2 CTAs/SM
#define NTHR 512
#define EPS 1e-6f
#define ESCALE 1024.0f
#define PERSIST_ROWS 5632            // 88 MB tagged evict_last

__device__ __align__(16) __half g_E[(size_t)NN * NN];          // 128 MB
__device__ __align__(16) float  g_eu[NN];                      // eu/1024 (final)
__device__ __align__(16) float  g_ev[NN];                      // fp32 ev (final)
__device__ __align__(16) __half g_evh[NN];                     // ev/32 (hot loop)
__device__ __align__(16) __half g_parth[(size_t)NCTAS * NN];   // 4.85 MB fp16

// ---- L2 evict_last policy helpers -----------------------------------------
__device__ __forceinline__ uint64_t policy_evict_last() {
    uint64_t pol;
    asm("createpolicy.fractional.L2::evict_last.b64 %0, 1.0;" : "=l"(pol));
    return pol;
}
__device__ __forceinline__ uint4 ldg_pol(const uint4* p, uint64_t pol) {
    uint4 v;
    asm volatile("ld.global.L2::cache_hint.v4.b32 {%0,%1,%2,%3}, [%4], %5;"
                 : "=r"(v.x), "=r"(v.y), "=r"(v.z), "=r"(v.w)
                 : "l"(p), "l"(pol));
    return v;
}
__device__ __forceinline__ void stg_pol(uint4* p, uint4 v, uint64_t pol) {
    asm volatile("st.global.L2::cache_hint.v4.b32 [%0], {%1,%2,%3,%4}, %5;"
                 :: "l"(p), "r"(v.x), "r"(v.y), "r"(v.z), "r"(v.w), "l"(pol)
                 : "memory");
}

// FMA-only exp for x in [-15, 0]
__device__ __forceinline__ float fast_exp_neg(float x) {
    const float LOG2E = 1.4426950408889634f;
    float t = x * LOG2E;
    float n = rintf(t);
    float f = t - n;
    float p = 1.5403530393381608e-4f;
    p = fmaf(p, f, 1.3333558146428443e-3f);
    p = fmaf(p, f, 9.6181291076284770e-3f);
    p = fmaf(p, f, 5.5504108664821580e-2f);
    p = fmaf(p, f, 2.4022650695910070e-1f);
    p = fmaf(p, f, 6.9314718055994530e-1f);
    p = fmaf(p, f, 1.0f);
    return p * __int_as_float(((int)n + 127) << 23);
}

// ---------------------------------------------------------------------------
__global__ void precompute_kernel(const float* __restrict__ C) {
    size_t g = (size_t)blockIdx.x * blockDim.x + threadIdx.x;
    const float4* C4 = reinterpret_cast<const float4*>(C);
    float4 c0 = C4[2 * g];
    float4 c1 = C4[2 * g + 1];
    uint4 o;
    __half2* h = reinterpret_cast<__half2*>(&o);
    h[0] = __floats2half2_rn(ESCALE * fast_exp_neg(-10.0f * c0.x),
                             ESCALE * fast_exp_neg(-10.0f * c0.y));
    h[1] = __floats2half2_rn(ESCALE * fast_exp_neg(-10.0f * c0.z),
                             ESCALE * fast_exp_neg(-10.0f * c0.w));
    h[2] = __floats2half2_rn(ESCALE * fast_exp_neg(-10.0f * c1.x),
                             ESCALE * fast_exp_neg(-10.0f * c1.y));
    h[3] = __floats2half2_rn(ESCALE * fast_exp_neg(-10.0f * c1.z),
                             ESCALE * fast_exp_neg(-10.0f * c1.w));
    uint4* dst = reinterpret_cast<uint4*>(g_E) + g;
    int row = (int)(g >> 10);                    // g / NC4
    if (row < PERSIST_ROWS) {
        stg_pol(dst, o, policy_evict_last());
    } else {
        *dst = o;
    }
    if (g < NN) {
        const float E1 = 2.718281828459045f;     // exp(v0), v0 = 1
        g_ev[g]  = E1;
        g_evh[g] = __float2half_rn(E1 * 0.03125f);
    }
}

// ---------------------------------------------------------------------------
// Fused iteration: 296 CTAs x 512 threads, 2 CTAs/SM, register double buffer.
// Thread t owns chunks t and t+512 of each row. 1 barrier per 2-row group.
// ---------------------------------------------------------------------------
__global__ void __launch_bounds__(NTHR, 2)
iter_kernel(const float* __restrict__ d) {
    __shared__ float wpart[64];       // [2 parities][32]

    const int tid  = threadIdx.x;
    const int wid  = tid >> 5;
    const int lane = tid & 31;
    const int cta  = blockIdx.x;
    const int ng   = (NGROUPS - cta + NCTAS - 1) / NCTAS;      // 13 or 14

    const uint4* Eg  = reinterpret_cast<const uint4*>(g_E);
    const uint4* EVH = reinterpret_cast<const uint4*>(g_evh);
    const uint64_t pol = policy_evict_last();

    // ev/32 for this thread's 16 columns (8 half2 regs, loop-invariant)
    __half2 va2[4], vb2[4];
    {
        uint4 v = __ldg(EVH + tid);
        const __half2* hv = reinterpret_cast<const __half2*>(&v);
#pragma unroll
        for (int k = 0; k < 4; ++k) va2[k] = hv[k];
        v = __ldg(EVH + tid + 512);
        hv = reinterpret_cast<const __half2*>(&v);
#pragma unroll
        for (int k = 0; k < 4; ++k) vb2[k] = hv[k];
    }

    __half2 cacc[8];
#pragma unroll
    for (int k = 0; k < 8; ++k) cacc[k] = __float2half2_rn(0.0f);

    uint4 xA0, xB0, xA1, xB1;         // current buffer
    uint4 yA0, yB0, yA1, yB1;         // next buffer

    auto loadg = [&](int t, uint4& a0, uint4& b0, uint4& a1, uint4& b1) {
        const int grow0 = (cta + t * NCTAS) * GROWS;
        const uint4* s0 = Eg + (size_t)grow0 * NC4;
        const uint4* s1 = s0 + NC4;
        if (grow0 < PERSIST_ROWS) {           // tagged region: evict_last
            a0 = ldg_pol(s0 + tid, pol);
            b0 = ldg_pol(s0 + tid + 512, pol);
            a1 = ldg_pol(s1 + tid, pol);
            b1 = ldg_pol(s1 + tid + 512, pol);
        } else {                              // streaming region
            a0 = __ldcs(s0 + tid);
            b0 = __ldcs(s0 + tid + 512);
            a1 = __ldcs(s1 + tid);
            b1 = __ldcs(s1 + tid + 512);
        }
    };

    auto process = [&](int t, const uint4& eA0, const uint4& eB0,
                              const uint4& eA1, const uint4& eB1) {
        const int grow0 = (cta + t * NCTAS) * GROWS;
        float* wp = wpart + (t & 1) * 32;
        const __half2* a0 = reinterpret_cast<const __half2*>(&eA0);
        const __half2* b0 = reinterpret_cast<const __half2*>(&eB0);
        const __half2* a1 = reinterpret_cast<const __half2*>(&eA1);
        const __half2* b1 = reinterpret_cast<const __half2*>(&eB1);

        // ---- phase 1: rowsum partials in HFMA2 ----------------------------
        __half2 rp0 = __float2half2_rn(0.0f);
        __half2 rp1 = __float2half2_rn(0.0f);
#pragma unroll
        for (int k = 0; k < 4; ++k) {
            rp0 = __hfma2(a0[k], va2[k], rp0);
            rp0 = __hfma2(b0[k], vb2[k], rp0);
            rp1 = __hfma2(a1[k], va2[k], rp1);
            rp1 = __hfma2(b1[k], vb2[k], rp1);
        }
        float2 f0 = __half22float2(rp0);
        float2 f1 = __half22float2(rp1);
        float s0 = f0.x + f0.y;
        float s1 = f1.x + f1.y;
#pragma unroll
        for (int o = 16; o > 0; o >>= 1) {
            s0 += __shfl_down_sync(0xFFFFFFFFu, s0, o);
            s1 += __shfl_down_sync(0xFFFFFFFFu, s1, o);
        }
        if (lane == 0) {
            wp[wid]      = s0;
            wp[16 + wid] = s1;
        }
        __syncthreads();              // the only barrier in the group

        // ---- xor-butterfly over the 32 warp partials (fixed tree) ---------
        float v = wp[lane];
#pragma unroll
        for (int o = 1; o < 16; o <<= 1)
            v += __shfl_xor_sync(0xFFFFFFFFu, v, o);
        float w = __shfl_xor_sync(0xFFFFFFFFu, v, 16);
        float rs0 = (lane < 16) ? v : w;
        float rs1 = (lane < 16) ? w : v;
        float eu0 = __fdividef((__ldg(d + grow0)     + EPS) * 32.0f, rs0);
        float eu1 = __fdividef((__ldg(d + grow0 + 1) + EPS) * 32.0f, rs1);
        if (tid == 0) {
            g_eu[grow0]     = eu0 * (1.0f / 1024.0f);
            g_eu[grow0 + 1] = eu1 * (1.0f / 1024.0f);
        }

        // ---- phase 2: fp16 column accumulation ----------------------------
        __half2 u0 = __float2half2_rn(eu0);
        __half2 u1 = __float2half2_rn(eu1);
#pragma unroll
        for (int k = 0; k < 4; ++k) {
            cacc[k]     = __hfma2(a0[k], u0, cacc[k]);
            cacc[4 + k] = __hfma2(b0[k], u0, cacc[4 + k]);
            cacc[k]     = __hfma2(a1[k], u1, cacc[k]);
            cacc[4 + k] = __hfma2(b1[k], u1, cacc[4 + k]);
        }
    };

    loadg(0, xA0, xB0, xA1, xB1);
    for (int t = 0; t < ng; t += 2) {
        if (t + 1 < ng) loadg(t + 1, yA0, yB0, yA1, yB1);
        process(t, xA0, xB0, xA1, xB1);
        if (t + 1 < ng) {
            if (t + 2 < ng) loadg(t + 2, xA0, xB0, xA1, xB1);
            process(t + 1, yA0, yB0, yA1, yB1);
        }
    }

    // write fp16 partials (streaming stores)
    uint4 o0, o1;
    __half2* p0 = reinterpret_cast<__half2*>(&o0);
    __half2* p1 = reinterpret_cast<__half2*>(&o1);
#pragma unroll
    for (int k = 0; k < 4; ++k) { p0[k] = cacc[k]; p1[k] = cacc[4 + k]; }
    uint4* PH = reinterpret_cast<uint4*>(g_parth + (size_t)cta * NN);
    __stcs(PH + tid,       o0);
    __stcs(PH + tid + 512, o1);
}

// ---------------------------------------------------------------------------
// ev from fp16 partials: sum 296 partials in fp32, fixed order.
// grid = 32 CTAs x 256 threads; thread (slice 0..7, chunk 0..31).
// ---------------------------------------------------------------------------
__global__ void col_reduce_kernel(const float* __restrict__ s) {
    __shared__ float red[8][32][8];
    const int g     = threadIdx.x & 31;
    const int slice = threadIdx.x >> 5;
    const int chunk = blockIdx.x * 32 + g;       // 0..1023 (8 cols each)
    const uint4* PH = reinterpret_cast<const uint4*>(g_parth);
    float acc[8] = {0.f, 0.f, 0.f, 0.f, 0.f, 0.f, 0.f, 0.f};
#pragma unroll
    for (int k = 0; k < 37; ++k) {
        uint4 v = __ldcs(PH + (size_t)(slice * 37 + k) * NC4 + chunk);
        const __half2* h = reinterpret_cast<const __half2*>(&v);
#pragma unroll
        for (int m = 0; m < 4; ++m) {
            float2 f = __half22float2(h[m]);
            acc[2 * m]     += f.x;
            acc[2 * m + 1] += f.y;
        }
    }
#pragma unroll
    for (int m = 0; m < 8; ++m) red[slice][g][m] = acc[m];
    __syncthreads();
    if (slice == 0) {
        float t[8];
#pragma unroll
        for (int m = 0; m < 8; ++m) t[m] = red[0][g][m];
#pragma unroll
        for (int q = 1; q < 8; ++q)                 // fixed order
#pragma unroll
            for (int m = 0; m < 8; ++m) t[m] += red[q][g][m];
        const int j0 = chunk * 8;
        float ev[8];
#pragma unroll
        for (int m = 0; m < 8; ++m)
            ev[m] = (s[j0 + m] + EPS) * 1024.0f / t[m];
        float4* EV4 = reinterpret_cast<float4*>(g_ev + j0);
        EV4[0] = make_float4(ev[0], ev[1], ev[2], ev[3]);
        EV4[1] = make_float4(ev[4], ev[5], ev[6], ev[7]);
        uint4 hv;
        __half2* hp = reinterpret_cast<__half2*>(&hv);
#pragma unroll
        for (int m = 0; m < 4; ++m)
            hp[m] = __floats2half2_rn(ev[2 * m] * 0.03125f,
                                      ev[2 * m + 1] * 0.03125f);
        *reinterpret_cast<uint4*>(g_evh + j0) = hv;
    }
}

// ---------------------------------------------------------------------------
// Final: P_ij = (eu_i/1024) * E'_ij * ev_j   (fp32 eu/ev)
// ---------------------------------------------------------------------------
__global__ void final_kernel(float* __restrict__ out) {
    size_t idx = (size_t)blockIdx.x * blockDim.x + threadIdx.x;
    int row = (int)(idx / NC4);
    int c8  = (int)(idx % NC4);
    float u = g_eu[row];
    const float4* ev4 = reinterpret_cast<const float4*>(g_ev);
    float4 v0 = ev4[2 * c8];
    float4 v1 = ev4[2 * c8 + 1];
    uint4 e = __ldg(reinterpret_cast<const uint4*>(g_E) + idx);
    const __half2* hp = reinterpret_cast<const __half2*>(&e);
    float2 f0 = __half22float2(hp[0]);
    float2 f1 = __half22float2(hp[1]);
    float2 f2 = __half22float2(hp[2]);
    float2 f3 = __half22float2(hp[3]);
    float4 p0, p1;
    p0.x = u * f0.x * v0.x;  p0.y = u * f0.y * v0.y;
    p0.z = u * f1.x * v0.z;  p0.w = u * f1.y * v0.w;
    p1.x = u * f2.x * v1.x;  p1.y = u * f2.y * v1.y;
    p1.z = u * f3.x * v1.z;  p1.w = u * f3.y * v1.w;
    float4* O4 = reinterpret_cast<float4*>(out);
    O4[2 * idx]     = p0;
    O4[2 * idx + 1] = p1;
}

// ---------------------------------------------------------------------------
extern "C" void kernel_launch(void* const* d_in, const int* in_sizes, int n_in,
                              void* d_out, int out_size) {
    const float* C = (const float*)d_in[0];
    const float* d = (const float*)d_in[1];
    const float* s = (const float*)d_in[2];
    float* out = (float*)d_out;

    const int VBLOCKS = (NN * NC4) / 256;    // 32768

    precompute_kernel<<<VBLOCKS, 256>>>(C);

    for (int it = 0; it < 50; ++it) {
        iter_kernel<<<NCTAS, NTHR>>>(d);
        col_reduce_kernel<<<32, 256>>>(s);
    }

    final_kernel<<<VBLOCKS, 256>>>(out);
}